// round 5
// baseline (speedup 1.0000x reference)
#include <cuda_runtime.h>
#include <math.h>

#define NMAX 4096
#define BMAX 4096
#define ONE_THIRD2 (2.0f / 3.0f)
#define FOUR_THIRDS (4.0f / 3.0f)

// Scratch (no allocations allowed)
__device__ float  g_min_dist[NMAX];
__device__ float  g_params[2];          // [0]=1/dil, [1]=dil^2
__device__ float4 g_minv[2 * BMAX];     // per query: (i00,i01,i02,i11),(i12,i22,qx,qy)

// ---------------------------------------------------------------------------
// Kernel 1: per-node nearest-neighbor distance. One WARP per node.
// ---------------------------------------------------------------------------
__global__ __launch_bounds__(256) void min_dist_kernel(const float2* __restrict__ nodes, int N) {
    __shared__ float2 s_nodes[NMAX];
    const int tid = threadIdx.x;
    const int nst = (N < NMAX) ? N : NMAX;
    for (int i = tid; i < nst; i += 256) s_nodes[i] = nodes[i];
    __syncthreads();

    const int lane = tid & 31;
    const int i = blockIdx.x * 8 + (tid >> 5);
    if (i >= N) return;
    const float2 xi = (i < NMAX) ? s_nodes[i] : nodes[i];
    float m = 3.4e38f;
    #pragma unroll 4
    for (int j = lane; j < N; j += 32) {
        const float2 nd = (j < NMAX) ? s_nodes[j] : __ldg(&nodes[j]);
        float dx = xi.x - nd.x;
        float dy = xi.y - nd.y;
        float d2 = fmaf(dy, dy, dx * dx);
        if (j != i) m = fminf(m, d2);
    }
    #pragma unroll
    for (int o = 16; o; o >>= 1) m = fminf(m, __shfl_xor_sync(0xffffffffu, m, o));
    if (lane == 0) g_min_dist[i] = sqrtf(m);
}

// ---------------------------------------------------------------------------
// Cubic spline weight (matches reference piecewise formula + support mask)
// ---------------------------------------------------------------------------
__device__ __forceinline__ float cubic_w(float q) {
    float w;
    if (q <= 0.5f) w = ONE_THIRD2 + 4.f * q * q * (q - 1.f);
    else           w = FOUR_THIRDS + q * (-4.f + q * (4.f - FOUR_THIRDS * q));
    return (q <= 1.f) ? w : 0.f;
}

// ---------------------------------------------------------------------------
// Kernel 2: moments + inversion. One WARP per query point.
// Per block: stage nodes, deterministic dilation reduce, then each warp
// accumulates the 6-entry symmetric moment matrix for its query, shuffle
// reduces, and lane 0 performs the fp64 adjugate inversion -> g_minv.
// ---------------------------------------------------------------------------
__global__ __launch_bounds__(256) void moments_kernel(const float2* __restrict__ x,
                                                      const float2* __restrict__ nodes,
                                                      int B, int N) {
    __shared__ float2 s_nodes[NMAX];
    __shared__ float  s_red[256];

    const int tid = threadIdx.x;
    const int nst = (N < NMAX) ? N : NMAX;
    for (int i = tid; i < nst; i += 256) s_nodes[i] = nodes[i];

    // dilation: deterministic per-block tree reduce of g_min_dist (L2-hot)
    {
        float s = 0.f;
        for (int i = tid; i < N; i += 256) s += g_min_dist[i];
        s_red[tid] = s;
        __syncthreads();
        #pragma unroll
        for (int o = 128; o; o >>= 1) {
            if (tid < o) s_red[tid] += s_red[tid + o];
            __syncthreads();
        }
    }
    const float dil     = 2.5f * (s_red[0] / (float)N);
    const float inv_dil = 1.f / dil;
    const float dil2    = dil * dil;
    if (blockIdx.x == 0 && tid == 0) {
        g_params[0] = inv_dil;
        g_params[1] = dil2;
    }

    const int lane = tid & 31;
    const int qi = blockIdx.x * 8 + (tid >> 5);
    if (qi >= B) return;
    const float2 qv = x[qi];

    float a0 = 0.f, a1 = 0.f, a2 = 0.f, a3 = 0.f, a4 = 0.f, a5 = 0.f;
    #pragma unroll 2
    for (int n = lane; n < N; n += 32) {
        const float2 nd = (n < NMAX) ? s_nodes[n] : __ldg(&nodes[n]);
        float dx = qv.x - nd.x;
        float dy = qv.y - nd.y;
        float d2 = dx * dx + dy * dy + 1e-10f;
        if (d2 <= dil2) {
            float w = cubic_w(sqrtf(d2) * inv_dil);
            a0 += w;
            a1 = fmaf(w, dx, a1);
            a2 = fmaf(w, dy, a2);
            a3 = fmaf(w * dx, dx, a3);
            a4 = fmaf(w * dx, dy, a4);
            a5 = fmaf(w * dy, dy, a5);
        }
    }
    #pragma unroll
    for (int o = 16; o; o >>= 1) {
        a0 += __shfl_xor_sync(0xffffffffu, a0, o);
        a1 += __shfl_xor_sync(0xffffffffu, a1, o);
        a2 += __shfl_xor_sync(0xffffffffu, a2, o);
        a3 += __shfl_xor_sync(0xffffffffu, a3, o);
        a4 += __shfl_xor_sync(0xffffffffu, a4, o);
        a5 += __shfl_xor_sync(0xffffffffu, a5, o);
    }
    if (lane == 0) {
        double a = (double)a0 + 1e-5, b = (double)a1, c = (double)a2;
        double d = (double)a3 + 1e-5, e = (double)a4, f = (double)a5 + 1e-5;
        double c00 = d * f - e * e;
        double c01 = c * e - b * f;
        double c02 = b * e - c * d;
        double det = a * c00 + b * c01 + c * c02;
        double id  = 1.0 / det;
        float i00 = (float)(c00 * id);
        float i01 = (float)(c01 * id);
        float i02 = (float)(c02 * id);
        float i11 = (float)((a * f - c * c) * id);
        float i12 = (float)((b * c - a * e) * id);
        float i22 = (float)((a * d - b * b) * id);
        g_minv[2 * qi]     = make_float4(i00, i01, i02, i11);
        g_minv[2 * qi + 1] = make_float4(i12, i22, qv.x, qv.y);
    }
}

// ---------------------------------------------------------------------------
// Kernel 3: pure streaming output writer. Zero smem, low regs -> max occupancy.
// grid = (ceil(N/1024), B); each thread handles 4 consecutive n for one b:
// 2 broadcast float4 loads (M_inv), 2 float4 node loads (L2-hot), trivial FMA,
// 3 coalesced STG.128 streaming stores.
// ---------------------------------------------------------------------------
__global__ __launch_bounds__(256) void out_kernel(const float2* __restrict__ nodes,
                                                  float* __restrict__ out,
                                                  int B, int N) {
    const int b  = blockIdx.y;
    const int n0 = blockIdx.x * 1024 + threadIdx.x * 4;
    if (n0 >= N) return;

    const float4 m0 = g_minv[2 * b];
    const float4 m1 = g_minv[2 * b + 1];
    const float i00 = m0.x, i01 = m0.y, i02 = m0.z, i11 = m0.w;
    const float i12 = m1.x, i22 = m1.y, qx = m1.z, qy = m1.w;
    const float inv_dil = g_params[0];
    const float dil2    = g_params[1];

    const size_t BN = (size_t)B * (size_t)N;
    float* __restrict__ o0 = out + (size_t)b * (size_t)N;
    float* __restrict__ o1 = o0 + BN;
    float* __restrict__ o2 = o1 + BN;

    if (n0 + 3 < N) {
        // vectorized node loads: 4 float2 = 2 float4
        const float4 nA = __ldg((const float4*)(nodes + n0));
        const float4 nB = __ldg((const float4*)(nodes + n0 + 2));
        float ndx[4] = {nA.x, nA.z, nB.x, nB.z};
        float ndy[4] = {nA.y, nA.w, nB.y, nB.w};
        float rp[4], rx[4], ry[4];
        #pragma unroll
        for (int j = 0; j < 4; j++) {
            float dx = qx - ndx[j];
            float dy = qy - ndy[j];
            float d2 = dx * dx + dy * dy + 1e-10f;
            if (d2 <= dil2) {
                float w = cubic_w(sqrtf(d2) * inv_dil);
                rp[j] =  w * (i00 + i01 * dx + i02 * dy);
                rx[j] = -(w * (i01 + i11 * dx + i12 * dy));
                ry[j] = -(w * (i02 + i12 * dx + i22 * dy));
            } else {
                rp[j] = 0.f; rx[j] = 0.f; ry[j] = 0.f;
            }
        }
        __stcs((float4*)(o0 + n0), make_float4(rp[0], rp[1], rp[2], rp[3]));
        __stcs((float4*)(o1 + n0), make_float4(rx[0], rx[1], rx[2], rx[3]));
        __stcs((float4*)(o2 + n0), make_float4(ry[0], ry[1], ry[2], ry[3]));
    } else {
        for (int n = n0; n < N; n++) {
            const float2 nd = __ldg(&nodes[n]);
            float dx = qx - nd.x;
            float dy = qy - nd.y;
            float d2 = dx * dx + dy * dy + 1e-10f;
            float w = (d2 <= dil2) ? cubic_w(sqrtf(d2) * inv_dil) : 0.f;
            o0[n] =  w * (i00 + i01 * dx + i02 * dy);
            o1[n] = -(w * (i01 + i11 * dx + i12 * dy));
            o2[n] = -(w * (i02 + i12 * dx + i22 * dy));
        }
    }
}

// ---------------------------------------------------------------------------
// Launch: metadata order is {x, nodes}; output is [3, B, N] fp32.
// ---------------------------------------------------------------------------
extern "C" void kernel_launch(void* const* d_in, const int* in_sizes, int n_in,
                              void* d_out, int out_size) {
    const float2* x     = (const float2*)d_in[0];
    const float2* nodes = (const float2*)d_in[1];
    float* out = (float*)d_out;
    const int B = in_sizes[0] / 2;
    const int N = in_sizes[1] / 2;

    min_dist_kernel<<<(N + 7) / 8, 256>>>(nodes, N);
    moments_kernel<<<(B + 7) / 8, 256>>>(x, nodes, B, N);

    dim3 grid((N + 1023) / 1024, B);
    out_kernel<<<grid, 256>>>(nodes, out, B, N);
}

// round 6
// speedup vs baseline: 1.0352x; 1.0352x over previous
#include <cuda_runtime.h>
#include <math.h>

#define NMAX 4096
#define ONE_THIRD2 (2.0f / 3.0f)
#define FOUR_THIRDS (4.0f / 3.0f)

// Scratch (no allocations allowed)
__device__ float g_part[4096];   // per-block partial sums of nearest-neighbor dist

// ---------------------------------------------------------------------------
// Cubic spline weight (matches reference piecewise formula + support mask)
// ---------------------------------------------------------------------------
__device__ __forceinline__ float cubic_w(float q) {
    float w;
    if (q <= 0.5f) w = ONE_THIRD2 + 4.f * q * q * (q - 1.f);
    else           w = FOUR_THIRDS + q * (-4.f + q * (4.f - FOUR_THIRDS * q));
    return (q <= 1.f) ? w : 0.f;
}

// ---------------------------------------------------------------------------
// Kernel 1a (fast, N <= NMAX): warp-per-node NN distance from a float4 smem
// tile (one LDS.128 serves two candidate pairs). Block writes the
// deterministic sum of its 8 node distances to g_part[blockIdx].
// ---------------------------------------------------------------------------
__global__ __launch_bounds__(256) void min_dist_fast(const float2* __restrict__ nodes, int N) {
    __shared__ float4 s_n4[NMAX / 2];
    __shared__ float  s_d[8];
    const int tid = threadIdx.x;
    const int N2 = (N + 1) >> 1;

    const float4* n4 = (const float4*)nodes;
    for (int i = tid; i < N / 2; i += 256) s_n4[i] = n4[i];
    if ((N & 1) && tid == 0) {
        float2 last = nodes[N - 1];
        s_n4[N / 2] = make_float4(last.x, last.y, 1e18f, 1e18f);  // pad: huge d2
    }
    __syncthreads();

    const int lane = tid & 31;
    const int wid  = tid >> 5;
    const int i    = blockIdx.x * 8 + wid;
    float m = 3.4e38f;
    if (i < N) {
        const float2 xi = ((const float2*)s_n4)[i];
        #pragma unroll 4
        for (int jj = lane; jj < N2; jj += 32) {
            const float4 v = s_n4[jj];
            const int j0 = jj * 2, j1 = j0 + 1;
            float dx0 = xi.x - v.x, dy0 = xi.y - v.y;
            float dx1 = xi.x - v.z, dy1 = xi.y - v.w;
            float d0 = fmaf(dx0, dx0, dy0 * dy0);
            float d1 = fmaf(dx1, dx1, dy1 * dy1);
            if (j0 != i) m = fminf(m, d0);
            if (j1 != i) m = fminf(m, d1);
        }
        #pragma unroll
        for (int o = 16; o; o >>= 1) m = fminf(m, __shfl_xor_sync(0xffffffffu, m, o));
    }
    if (lane == 0) s_d[wid] = (i < N) ? sqrtf(m) : 0.f;
    __syncthreads();
    if (tid == 0) {
        float s = 0.f;
        #pragma unroll
        for (int w = 0; w < 8; w++) s += s_d[w];
        g_part[blockIdx.x] = s;
    }
}

// ---------------------------------------------------------------------------
// Kernel 1b (generic, N > NMAX): same contract, nodes via __ldg (no smem tile).
// ---------------------------------------------------------------------------
__global__ __launch_bounds__(256) void min_dist_generic(const float2* __restrict__ nodes, int N) {
    __shared__ float s_d[8];
    const int tid = threadIdx.x;
    const int lane = tid & 31;
    const int wid  = tid >> 5;
    const int i    = blockIdx.x * 8 + wid;
    float m = 3.4e38f;
    if (i < N) {
        const float2 xi = __ldg(&nodes[i]);
        for (int j = lane; j < N; j += 32) {
            const float2 nd = __ldg(&nodes[j]);
            float dx = xi.x - nd.x, dy = xi.y - nd.y;
            float d2 = fmaf(dx, dx, dy * dy);
            if (j != i) m = fminf(m, d2);
        }
        #pragma unroll
        for (int o = 16; o; o >>= 1) m = fminf(m, __shfl_xor_sync(0xffffffffu, m, o));
    }
    if (lane == 0) s_d[wid] = (i < N) ? sqrtf(m) : 0.f;
    __syncthreads();
    if (tid == 0) {
        float s = 0.f;
        #pragma unroll
        for (int w = 0; w < 8; w++) s += s_d[w];
        g_part[blockIdx.x] = s;
    }
}

// ---------------------------------------------------------------------------
// Kernel 2: FUSED moments + inversion + streaming output. One block per query.
// - deterministic dilation from g_part (L2-hot, fixed-order tree)
// - pass 1: 6-entry symmetric moment matrix over L1-resident nodes
// - thread 0: fp64 adjugate inversion
// - pass 2: coalesced float4 streaming stores of phi / phi_x / phi_y
// Tiny smem (~1.3 KB) -> many resident blocks, so stores from some blocks
// overlap compute phases of others; DRAM never idles.
// ---------------------------------------------------------------------------
__global__ __launch_bounds__(256) void rkpm_fused(const float2* __restrict__ x,
                                                  const float2* __restrict__ nodes,
                                                  float* __restrict__ out,
                                                  int B, int N, int nblk) {
    __shared__ float s_red[256];
    __shared__ float s_part[8][6];
    __shared__ float s_minv[6];
    __shared__ float s_p[2];   // inv_dil, dil2

    const int tid = threadIdx.x;
    const int b   = blockIdx.x;

    // ---- dilation (deterministic, per block) ----
    {
        float s = 0.f;
        for (int i = tid; i < nblk; i += 256) s += g_part[i];
        s_red[tid] = s;
        __syncthreads();
        #pragma unroll
        for (int o = 128; o; o >>= 1) {
            if (tid < o) s_red[tid] += s_red[tid + o];
            __syncthreads();
        }
        if (tid == 0) {
            float dil = 2.5f * (s_red[0] / (float)N);
            s_p[0] = 1.f / dil;
            s_p[1] = dil * dil;
        }
        __syncthreads();
    }
    const float inv_dil = s_p[0];
    const float dil2    = s_p[1];
    const float2 qv = __ldg(&x[b]);

    // ---- pass 1: moment matrix ----
    float a0 = 0.f, a1 = 0.f, a2 = 0.f, a3 = 0.f, a4 = 0.f, a5 = 0.f;
    for (int n = tid; n < N; n += 256) {
        const float2 nd = __ldg(&nodes[n]);
        float dx = qv.x - nd.x;
        float dy = qv.y - nd.y;
        float d2 = dx * dx + dy * dy + 1e-10f;
        if (d2 <= dil2) {
            float w = cubic_w(sqrtf(d2) * inv_dil);
            a0 += w;
            a1 = fmaf(w, dx, a1);
            a2 = fmaf(w, dy, a2);
            a3 = fmaf(w * dx, dx, a3);
            a4 = fmaf(w * dx, dy, a4);
            a5 = fmaf(w * dy, dy, a5);
        }
    }
    #pragma unroll
    for (int o = 16; o; o >>= 1) {
        a0 += __shfl_xor_sync(0xffffffffu, a0, o);
        a1 += __shfl_xor_sync(0xffffffffu, a1, o);
        a2 += __shfl_xor_sync(0xffffffffu, a2, o);
        a3 += __shfl_xor_sync(0xffffffffu, a3, o);
        a4 += __shfl_xor_sync(0xffffffffu, a4, o);
        a5 += __shfl_xor_sync(0xffffffffu, a5, o);
    }
    if ((tid & 31) == 0) {
        const int w = tid >> 5;
        s_part[w][0] = a0; s_part[w][1] = a1; s_part[w][2] = a2;
        s_part[w][3] = a3; s_part[w][4] = a4; s_part[w][5] = a5;
    }
    __syncthreads();

    // ---- fp64 adjugate inversion (thread 0) ----
    if (tid == 0) {
        float m[6];
        #pragma unroll
        for (int c = 0; c < 6; c++) {
            float s = 0.f;
            #pragma unroll
            for (int w = 0; w < 8; w++) s += s_part[w][c];
            m[c] = s;
        }
        double a = (double)m[0] + 1e-5, bb = (double)m[1], c = (double)m[2];
        double d = (double)m[3] + 1e-5, e  = (double)m[4], f = (double)m[5] + 1e-5;
        double c00 = d * f - e * e;
        double c01 = c * e - bb * f;
        double c02 = bb * e - c * d;
        double det = a * c00 + bb * c01 + c * c02;
        double id  = 1.0 / det;
        s_minv[0] = (float)(c00 * id);
        s_minv[1] = (float)(c01 * id);
        s_minv[2] = (float)(c02 * id);
        s_minv[3] = (float)((a * f - c * c) * id);
        s_minv[4] = (float)((bb * c - a * e) * id);
        s_minv[5] = (float)((a * d - bb * bb) * id);
    }
    __syncthreads();

    const float i00 = s_minv[0], i01 = s_minv[1], i02 = s_minv[2];
    const float i11 = s_minv[3], i12 = s_minv[4], i22 = s_minv[5];
    const float qx = qv.x, qy = qv.y;

    const size_t BN = (size_t)B * (size_t)N;
    float* __restrict__ o0 = out + (size_t)b * (size_t)N;
    float* __restrict__ o1 = o0 + BN;
    float* __restrict__ o2 = o1 + BN;

    // ---- pass 2: streaming outputs ----
    if ((N & 3) == 0) {
        for (int base = tid * 4; base < N; base += 1024) {
            const float4 nA = __ldg((const float4*)(nodes + base));
            const float4 nB = __ldg((const float4*)(nodes + base + 2));
            const float ndx[4] = {nA.x, nA.z, nB.x, nB.z};
            const float ndy[4] = {nA.y, nA.w, nB.y, nB.w};
            float rp[4], rx[4], ry[4];
            #pragma unroll
            for (int j = 0; j < 4; j++) {
                float dx = qx - ndx[j];
                float dy = qy - ndy[j];
                float d2 = dx * dx + dy * dy + 1e-10f;
                if (d2 <= dil2) {
                    float w = cubic_w(sqrtf(d2) * inv_dil);
                    rp[j] =  w * (i00 + i01 * dx + i02 * dy);
                    rx[j] = -(w * (i01 + i11 * dx + i12 * dy));
                    ry[j] = -(w * (i02 + i12 * dx + i22 * dy));
                } else {
                    rp[j] = 0.f; rx[j] = 0.f; ry[j] = 0.f;
                }
            }
            __stcs((float4*)(o0 + base), make_float4(rp[0], rp[1], rp[2], rp[3]));
            __stcs((float4*)(o1 + base), make_float4(rx[0], rx[1], rx[2], rx[3]));
            __stcs((float4*)(o2 + base), make_float4(ry[0], ry[1], ry[2], ry[3]));
        }
    } else {
        for (int n = tid; n < N; n += 256) {
            const float2 nd = __ldg(&nodes[n]);
            float dx = qx - nd.x;
            float dy = qy - nd.y;
            float d2 = dx * dx + dy * dy + 1e-10f;
            float w = (d2 <= dil2) ? cubic_w(sqrtf(d2) * inv_dil) : 0.f;
            o0[n] =  w * (i00 + i01 * dx + i02 * dy);
            o1[n] = -(w * (i01 + i11 * dx + i12 * dy));
            o2[n] = -(w * (i02 + i12 * dx + i22 * dy));
        }
    }
}

// ---------------------------------------------------------------------------
// Launch: metadata order is {x, nodes}; output is [3, B, N] fp32.
// ---------------------------------------------------------------------------
extern "C" void kernel_launch(void* const* d_in, const int* in_sizes, int n_in,
                              void* d_out, int out_size) {
    const float2* x     = (const float2*)d_in[0];
    const float2* nodes = (const float2*)d_in[1];
    float* out = (float*)d_out;
    const int B = in_sizes[0] / 2;
    const int N = in_sizes[1] / 2;

    int nblk = (N + 7) / 8;
    if (nblk > 4096) nblk = 4096;           // g_part capacity guard
    if (N <= NMAX) {
        min_dist_fast<<<nblk, 256>>>(nodes, N);
    } else {
        // generic path: cap blocks so g_part fits; each warp still covers its node
        nblk = (N + 7) / 8;
        if (nblk > 4096) nblk = 4096;
        min_dist_generic<<<nblk, 256>>>(nodes, N);
    }
    rkpm_fused<<<B, 256>>>(x, nodes, out, B, N, nblk);
}